// round 11
// baseline (speedup 1.0000x reference)
#include <cuda_runtime.h>

#define S 1024
#define G 10
#define F 5
#define B 8
#define C 3
#define KW (2*F+1)
#define RPB 4                 // rows per block
#define NXB (S / 256)         // x-positions per thread (4)

// ---------------------------------------------------------------------------
// Fused kernel: one block per (4 rows, batch). Prologue: separable 11x11
// edge-clamped conv (outer-product Gaussian) + y-interp for the 4 rows.
// Main loop: strided pixel mapping (x = tid + 256*p), warp-coalesced
// gathers/stores. launch_bounds(256,5) to push occupancy to 40 warps/SM.
// ---------------------------------------------------------------------------
__global__ __launch_bounds__(256, 5) void deform_fused_kernel(
        const float* __restrict__ xin,
        const float* __restrict__ ox,
        const float* __restrict__ oy,
        const float* __restrict__ w,
        const void* __restrict__ mm_p,
        float* __restrict__ out) {
    __shared__ float  sh[2][G][G];        // horizontal conv pass
    __shared__ float  sg[RPB][2][2][G];   // vertical pass at rows i0,i1 per row
    __shared__ float2 srow[RPB][G];       // final per-row coarse fields

    const int b     = blockIdx.y;
    const int ybase = blockIdx.x * RPB;
    const int tid   = threadIdx.x;

    // --- Phase 1: horizontal pass  h[ch][i][j] = sum_v w[F][v] * o[i][clamp(j+v-F)]
    if (tid < 2 * G * G) {
        int ch  = tid / (G * G);
        int rem = tid % (G * G);
        int i   = rem / G;
        int j   = rem % G;
        const float* o = (ch ? oy : ox) + b * G * G + i * G;
        float acc = 0.0f;
        #pragma unroll
        for (int v = 0; v < KW; v++) {
            int jj = min(max(j + v - F, 0), G - 1);
            acc = fmaf(__ldg(&w[F * KW + v]), __ldg(&o[jj]), acc);
        }
        sh[ch][i][j] = acc;
    }
    __syncthreads();

    // --- Phase 2: vertical pass at rows i0/i1 for each of the RPB rows
    if (tid < RPB * 2 * 2 * G) {
        int j   = tid % G;
        int sel = (tid / G) & 1;
        int ch  = (tid / (2 * G)) & 1;
        int r   = tid / (4 * G);
        int y   = ybase + r;

        float srcy = fmaxf((y + 0.5f) * ((float)G / (float)S) - 0.5f, 0.0f);
        int i0 = min((int)srcy, G - 1);
        int row = sel ? min(i0 + 1, G - 1) : i0;

        // max_move may arrive as int32 or float32 — decode robustly.
        int raw = *(const int*)mm_p;
        float mmv = (raw >= 0 && raw < 1000000) ? (float)raw : __int_as_float(raw);
        float max_offset = 2.0f * mmv / (float)S;

        float wff = __ldg(&w[F * KW + F]);
        float acc = 0.0f;
        #pragma unroll
        for (int u = 0; u < KW; u++) {
            int ii = min(max(row + u - F, 0), G - 1);
            acc = fmaf(__ldg(&w[u * KW + F]), sh[ch][ii][j], acc);
        }
        acc *= max_offset / wff;  // separable: w[u][v] = w[u][F]*w[F][v]/w[F][F]
        acc = fminf(fmaxf(acc, -max_offset), max_offset);
        sg[r][ch][sel][j] = acc;
    }
    __syncthreads();

    // --- Phase 3: y-interpolate each row's field
    if (tid < RPB * G) {
        int r = tid / G;
        int j = tid % G;
        int y = ybase + r;
        float srcy = fmaxf((y + 0.5f) * ((float)G / (float)S) - 0.5f, 0.0f);
        int i0 = min((int)srcy, G - 1);
        float wr = srcy - (float)i0;
        float gx = sg[r][0][0][j] * (1.0f - wr) + sg[r][0][1][j] * wr;
        float gy = sg[r][1][0][j] * (1.0f - wr) + sg[r][1][1][j] * wr;
        srow[r][j] = make_float2(gx, gy);
    }
    __syncthreads();

    // --- Main loop: strided pixels, coalesced gathers + stores
    const float* xb = xin + (size_t)b * C * S * S;
    float* obase    = out + (size_t)b * C * S * S;

    float Py[RPB];
    #pragma unroll
    for (int r = 0; r < RPB; r++)
        Py[r] = fmaf((float)(ybase + r), 2.0f / (float)(S - 1), -1.0f);

    #pragma unroll 2
    for (int p = 0; p < NXB; p++) {
        const int x = tid + p * 256;

        // x-dependent field interp — shared across the RPB rows
        float srcx = fmaxf((x + 0.5f) * ((float)G / (float)S) - 0.5f, 0.0f);
        int j0 = min((int)srcx, G - 1);
        int j1 = min(j0 + 1, G - 1);
        float wc  = srcx - (float)j0;
        float wcm = 1.0f - wc;
        float Px  = fmaf((float)x, 2.0f / (float)(S - 1), -1.0f);

        #pragma unroll
        for (int r = 0; r < RPB; r++) {
            float2 fa = srow[r][j0];
            float2 fb = srow[r][j1];
            float gx = fa.x * wcm + fb.x * wc;
            float gy = fa.y * wcm + fb.y * wc;

            float g0 = fminf(fmaxf(gx + Px, -1.0f), 1.0f);
            float g1 = fminf(fmaxf(gy + Py[r], -1.0f), 1.0f);

            // ((g+1)*S - 1) / 2 == g*512 + 511.5
            float ix = fmaf(g0, 512.0f, 511.5f);
            float iy = fmaf(g1, 512.0f, 511.5f);

            float fx = floorf(ix);
            float fy = floorf(iy);
            int x0 = (int)fx;
            int y0 = (int)fy;
            float wx = ix - fx;
            float wy = iy - fy;
            int x1 = x0 + 1;
            int y1 = y0 + 1;

            // ix in [-0.5, 1023.5]: only low of x0 / high of x1 can be OOB
            float wxa = (x0 >= 0)     ? (1.0f - wx) : 0.0f;
            float wxb = (x1 <= S - 1) ? wx          : 0.0f;
            float wya = (y0 >= 0)     ? (1.0f - wy) : 0.0f;
            float wyb = (y1 <= S - 1) ? wy          : 0.0f;

            int cx0 = max(x0, 0);
            int cx1 = min(x1, S - 1);
            int cy0 = max(y0, 0);
            int cy1 = min(y1, S - 1);

            float w00 = wya * wxa;
            float w01 = wya * wxb;
            float w10 = wyb * wxa;
            float w11 = wyb * wxb;

            int o00 = cy0 * S + cx0;
            int o01 = cy0 * S + cx1;
            int o10 = cy1 * S + cx0;
            int o11 = cy1 * S + cx1;

            size_t orow = (size_t)(ybase + r) * S + x;

            #pragma unroll
            for (int c = 0; c < C; c++) {
                const float* img = xb + (size_t)c * S * S;
                float v = img[o00] * w00 + img[o01] * w01
                        + img[o10] * w10 + img[o11] * w11;
                obase[(size_t)c * S * S + orow] = v;
            }
        }
    }
}

extern "C" void kernel_launch(void* const* d_in, const int* in_sizes, int n_in,
                              void* d_out, int out_size) {
    const float* x  = (const float*)d_in[0];
    const float* ox = (const float*)d_in[1];
    const float* oy = (const float*)d_in[2];
    const float* w  = (const float*)d_in[3];
    const void*  mm = d_in[4];

    dim3 grid(S / RPB, B);
    deform_fused_kernel<<<grid, 256>>>(x, ox, oy, w, mm, (float*)d_out);
}

// round 12
// speedup vs baseline: 1.0733x; 1.0733x over previous
#include <cuda_runtime.h>

#define S 1024
#define G 10
#define F 5
#define B 8
#define C 3
#define KW (2*F+1)
#define RPB 2                 // rows per deform block
#define NXB (S / 256)         // x-positions per thread (4)
#define YCHUNKS 8
#define YROWS (S / YCHUNKS)

// Per-row y-interpolated coarse field: (gx, gy) for each (b, y, j)
__device__ float2 g_rows[B][S][G];

// ---------------------------------------------------------------------------
// Prep: separable 11x11 edge-clamped conv (outer-product Gaussian) of the
// 10x10 offsets, clip, then y-interp into per-row fields. grid=(B, YCHUNKS).
// ---------------------------------------------------------------------------
__global__ __launch_bounds__(256) void prep_kernel(const float* __restrict__ ox,
                                                   const float* __restrict__ oy,
                                                   const float* __restrict__ w,
                                                   const void* __restrict__ mm_p) {
    __shared__ float sh[2][G][G];   // horizontal pass
    __shared__ float sc[2][G][G];   // full smoothed+clipped field

    const int b     = blockIdx.x;
    const int chunk = blockIdx.y;
    const int tid   = threadIdx.x;

    // Phase 1: horizontal pass h[ch][i][j] = sum_v w[F][v] * o[i][clamp(j+v-F)]
    if (tid < 2 * G * G) {
        int ch  = tid / (G * G);
        int rem = tid % (G * G);
        int i   = rem / G;
        int j   = rem % G;
        const float* o = (ch ? oy : ox) + b * G * G + i * G;
        float acc = 0.0f;
        #pragma unroll
        for (int v = 0; v < KW; v++) {
            int jj = min(max(j + v - F, 0), G - 1);
            acc = fmaf(__ldg(&w[F * KW + v]), __ldg(&o[jj]), acc);
        }
        sh[ch][i][j] = acc;
    }
    __syncthreads();

    // Phase 2: vertical pass, scale + clip (separable: w[u][v]=w[u][F]*w[F][v]/w[F][F])
    if (tid < 2 * G * G) {
        int ch  = tid / (G * G);
        int rem = tid % (G * G);
        int i   = rem / G;
        int j   = rem % G;

        int raw = *(const int*)mm_p;   // int32 or float32 — decode robustly
        float mmv = (raw >= 0 && raw < 1000000) ? (float)raw : __int_as_float(raw);
        float max_offset = 2.0f * mmv / (float)S;

        float wff = __ldg(&w[F * KW + F]);
        float acc = 0.0f;
        #pragma unroll
        for (int u = 0; u < KW; u++) {
            int ii = min(max(i + u - F, 0), G - 1);
            acc = fmaf(__ldg(&w[u * KW + F]), sh[ch][ii][j], acc);
        }
        acc *= max_offset / wff;
        acc = fminf(fmaxf(acc, -max_offset), max_offset);
        sc[ch][i][j] = acc;
    }
    __syncthreads();

    // Phase 3: expand along y for this chunk of rows
    for (int k = tid; k < YROWS * G; k += 256) {
        int yl = k / G;
        int j  = k % G;
        int y  = chunk * YROWS + yl;

        float srcy = fmaxf((y + 0.5f) * ((float)G / (float)S) - 0.5f, 0.0f);
        int i0 = min((int)srcy, G - 1);
        int i1 = min(i0 + 1, G - 1);
        float wr = srcy - (float)i0;

        float gx = sc[0][i0][j] * (1.0f - wr) + sc[0][i1][j] * wr;
        float gy = sc[1][i0][j] * (1.0f - wr) + sc[1][i1][j] * wr;
        g_rows[b][y][j] = make_float2(gx, gy);
    }
}

// ---------------------------------------------------------------------------
// Deform: one block per (2 rows, batch); prologue-free. Strided pixel mapping
// (x = tid + 256*p): warp-coalesced gathers and stores. 8 px/thread.
// ---------------------------------------------------------------------------
__global__ __launch_bounds__(256, 4) void deform_kernel(const float* __restrict__ xin,
                                                        float* __restrict__ out) {
    __shared__ float2 srow[RPB][G];

    const int b     = blockIdx.y;
    const int ybase = blockIdx.x * RPB;
    const int tid   = threadIdx.x;

    if (tid < RPB * G) {
        int r = tid / G;
        int j = tid % G;
        srow[r][j] = g_rows[b][ybase + r][j];
    }
    __syncthreads();

    const float* xb = xin + (size_t)b * C * S * S;
    float* obase    = out + (size_t)b * C * S * S;

    float Py[RPB];
    #pragma unroll
    for (int r = 0; r < RPB; r++)
        Py[r] = fmaf((float)(ybase + r), 2.0f / (float)(S - 1), -1.0f);

    #pragma unroll
    for (int p = 0; p < NXB; p++) {
        const int x = tid + p * 256;

        // x-dependent field interp — shared across the RPB rows
        float srcx = fmaxf((x + 0.5f) * ((float)G / (float)S) - 0.5f, 0.0f);
        int j0 = min((int)srcx, G - 1);
        int j1 = min(j0 + 1, G - 1);
        float wc  = srcx - (float)j0;
        float wcm = 1.0f - wc;
        float Px  = fmaf((float)x, 2.0f / (float)(S - 1), -1.0f);

        #pragma unroll
        for (int r = 0; r < RPB; r++) {
            float2 fa = srow[r][j0];
            float2 fb = srow[r][j1];
            float gx = fa.x * wcm + fb.x * wc;
            float gy = fa.y * wcm + fb.y * wc;

            float g0 = fminf(fmaxf(gx + Px, -1.0f), 1.0f);
            float g1 = fminf(fmaxf(gy + Py[r], -1.0f), 1.0f);

            // ((g+1)*S - 1) / 2 == g*512 + 511.5
            float ix = fmaf(g0, 512.0f, 511.5f);
            float iy = fmaf(g1, 512.0f, 511.5f);

            float fx = floorf(ix);
            float fy = floorf(iy);
            int x0 = (int)fx;
            int y0 = (int)fy;
            float wx = ix - fx;
            float wy = iy - fy;
            int x1 = x0 + 1;
            int y1 = y0 + 1;

            // ix in [-0.5, 1023.5]: only low of x0 / high of x1 can be OOB
            float wxa = (x0 >= 0)     ? (1.0f - wx) : 0.0f;
            float wxb = (x1 <= S - 1) ? wx          : 0.0f;
            float wya = (y0 >= 0)     ? (1.0f - wy) : 0.0f;
            float wyb = (y1 <= S - 1) ? wy          : 0.0f;

            int cx0 = max(x0, 0);
            int cx1 = min(x1, S - 1);
            int cy0 = max(y0, 0);
            int cy1 = min(y1, S - 1);

            float w00 = wya * wxa;
            float w01 = wya * wxb;
            float w10 = wyb * wxa;
            float w11 = wyb * wxb;

            int o00 = cy0 * S + cx0;
            int o01 = cy0 * S + cx1;
            int o10 = cy1 * S + cx0;
            int o11 = cy1 * S + cx1;

            size_t orow = (size_t)(ybase + r) * S + x;

            #pragma unroll
            for (int c = 0; c < C; c++) {
                const float* img = xb + (size_t)c * S * S;
                float v = img[o00] * w00 + img[o01] * w01
                        + img[o10] * w10 + img[o11] * w11;
                obase[(size_t)c * S * S + orow] = v;
            }
        }
    }
}

extern "C" void kernel_launch(void* const* d_in, const int* in_sizes, int n_in,
                              void* d_out, int out_size) {
    const float* x  = (const float*)d_in[0];
    const float* ox = (const float*)d_in[1];
    const float* oy = (const float*)d_in[2];
    const float* w  = (const float*)d_in[3];
    const void*  mm = d_in[4];

    prep_kernel<<<dim3(B, YCHUNKS), 256>>>(ox, oy, w, mm);

    dim3 grid(S / RPB, B);
    deform_kernel<<<grid, 256>>>(x, (float*)d_out);
}

// round 13
// speedup vs baseline: 1.0786x; 1.0050x over previous
#include <cuda_runtime.h>

#define S 1024
#define G 10
#define F 5
#define B 8
#define C 3
#define KW (2*F+1)
#define RPB 2                 // rows per deform block
#define NXB (S / 256)         // x-positions per thread (4)
#define YCHUNKS 8
#define YROWS (S / YCHUNKS)

// Per-row y-interpolated coarse field: (gx, gy) for each (b, y, j)
__device__ float2 g_rows[B][S][G];

// ---------------------------------------------------------------------------
// Prep: separable 11x11 edge-clamped conv (outer-product Gaussian) of the
// 10x10 offsets, clip, then y-interp into per-row fields. grid=(B, YCHUNKS).
// Signals PDL completion as soon as g_rows is written.
// ---------------------------------------------------------------------------
__global__ __launch_bounds__(256) void prep_kernel(const float* __restrict__ ox,
                                                   const float* __restrict__ oy,
                                                   const float* __restrict__ w,
                                                   const void* __restrict__ mm_p) {
    __shared__ float sh[2][G][G];   // horizontal pass
    __shared__ float sc[2][G][G];   // full smoothed+clipped field

    const int b     = blockIdx.x;
    const int chunk = blockIdx.y;
    const int tid   = threadIdx.x;

    // Phase 1: horizontal pass h[ch][i][j] = sum_v w[F][v] * o[i][clamp(j+v-F)]
    if (tid < 2 * G * G) {
        int ch  = tid / (G * G);
        int rem = tid % (G * G);
        int i   = rem / G;
        int j   = rem % G;
        const float* o = (ch ? oy : ox) + b * G * G + i * G;
        float acc = 0.0f;
        #pragma unroll
        for (int v = 0; v < KW; v++) {
            int jj = min(max(j + v - F, 0), G - 1);
            acc = fmaf(__ldg(&w[F * KW + v]), __ldg(&o[jj]), acc);
        }
        sh[ch][i][j] = acc;
    }
    __syncthreads();

    // Phase 2: vertical pass, scale + clip (separable: w[u][v]=w[u][F]*w[F][v]/w[F][F])
    if (tid < 2 * G * G) {
        int ch  = tid / (G * G);
        int rem = tid % (G * G);
        int i   = rem / G;
        int j   = rem % G;

        int raw = *(const int*)mm_p;   // int32 or float32 — decode robustly
        float mmv = (raw >= 0 && raw < 1000000) ? (float)raw : __int_as_float(raw);
        float max_offset = 2.0f * mmv / (float)S;

        float wff = __ldg(&w[F * KW + F]);
        float acc = 0.0f;
        #pragma unroll
        for (int u = 0; u < KW; u++) {
            int ii = min(max(i + u - F, 0), G - 1);
            acc = fmaf(__ldg(&w[u * KW + F]), sh[ch][ii][j], acc);
        }
        acc *= max_offset / wff;
        acc = fminf(fmaxf(acc, -max_offset), max_offset);
        sc[ch][i][j] = acc;
    }
    __syncthreads();

    // Phase 3: expand along y for this chunk of rows
    for (int k = tid; k < YROWS * G; k += 256) {
        int yl = k / G;
        int j  = k % G;
        int y  = chunk * YROWS + yl;

        float srcy = fmaxf((y + 0.5f) * ((float)G / (float)S) - 0.5f, 0.0f);
        int i0 = min((int)srcy, G - 1);
        int i1 = min(i0 + 1, G - 1);
        float wr = srcy - (float)i0;

        float gx = sc[0][i0][j] * (1.0f - wr) + sc[0][i1][j] * wr;
        float gy = sc[1][i0][j] * (1.0f - wr) + sc[1][i1][j] * wr;
        g_rows[b][y][j] = make_float2(gx, gy);
    }

    // PDL: make writes visible, then allow the dependent grid to proceed.
    __threadfence();
    cudaTriggerProgrammaticLaunchCompletion();
}

// ---------------------------------------------------------------------------
// Deform: one block per (2 rows, batch); prologue-free. Strided pixel mapping
// (x = tid + 256*p): warp-coalesced gathers and stores. 8 px/thread.
// Launched with programmatic stream serialization (PDL).
// ---------------------------------------------------------------------------
__global__ __launch_bounds__(256, 4) void deform_kernel(const float* __restrict__ xin,
                                                        float* __restrict__ out) {
    __shared__ float2 srow[RPB][G];

    const int b     = blockIdx.y;
    const int ybase = blockIdx.x * RPB;
    const int tid   = threadIdx.x;

    // Wait for prep's g_rows to be ready (PDL dependency).
    cudaGridDependencySynchronize();

    if (tid < RPB * G) {
        int r = tid / G;
        int j = tid % G;
        srow[r][j] = g_rows[b][ybase + r][j];
    }
    __syncthreads();

    const float* xb = xin + (size_t)b * C * S * S;
    float* obase    = out + (size_t)b * C * S * S;

    float Py[RPB];
    #pragma unroll
    for (int r = 0; r < RPB; r++)
        Py[r] = fmaf((float)(ybase + r), 2.0f / (float)(S - 1), -1.0f);

    #pragma unroll
    for (int p = 0; p < NXB; p++) {
        const int x = tid + p * 256;

        // x-dependent field interp — shared across the RPB rows
        float srcx = fmaxf((x + 0.5f) * ((float)G / (float)S) - 0.5f, 0.0f);
        int j0 = min((int)srcx, G - 1);
        int j1 = min(j0 + 1, G - 1);
        float wc  = srcx - (float)j0;
        float wcm = 1.0f - wc;
        float Px  = fmaf((float)x, 2.0f / (float)(S - 1), -1.0f);

        #pragma unroll
        for (int r = 0; r < RPB; r++) {
            float2 fa = srow[r][j0];
            float2 fb = srow[r][j1];
            float gx = fa.x * wcm + fb.x * wc;
            float gy = fa.y * wcm + fb.y * wc;

            float g0 = fminf(fmaxf(gx + Px, -1.0f), 1.0f);
            float g1 = fminf(fmaxf(gy + Py[r], -1.0f), 1.0f);

            // ((g+1)*S - 1) / 2 == g*512 + 511.5
            float ix = fmaf(g0, 512.0f, 511.5f);
            float iy = fmaf(g1, 512.0f, 511.5f);

            float fx = floorf(ix);
            float fy = floorf(iy);
            int x0 = (int)fx;
            int y0 = (int)fy;
            float wx = ix - fx;
            float wy = iy - fy;
            int x1 = x0 + 1;
            int y1 = y0 + 1;

            // ix in [-0.5, 1023.5]: only low of x0 / high of x1 can be OOB
            float wxa = (x0 >= 0)     ? (1.0f - wx) : 0.0f;
            float wxb = (x1 <= S - 1) ? wx          : 0.0f;
            float wya = (y0 >= 0)     ? (1.0f - wy) : 0.0f;
            float wyb = (y1 <= S - 1) ? wy          : 0.0f;

            int cx0 = max(x0, 0);
            int cx1 = min(x1, S - 1);
            int cy0 = max(y0, 0);
            int cy1 = min(y1, S - 1);

            float w00 = wya * wxa;
            float w01 = wya * wxb;
            float w10 = wyb * wxa;
            float w11 = wyb * wxb;

            // All per-batch offsets fit in int32 — avoid IMAD.WIDE chains.
            int o00 = cy0 * S + cx0;
            int o01 = cy0 * S + cx1;
            int o10 = cy1 * S + cx0;
            int o11 = cy1 * S + cx1;

            int orow = (ybase + r) * S + x;

            #pragma unroll
            for (int c = 0; c < C; c++) {
                const float* img = xb + c * (S * S);
                float v = img[o00] * w00 + img[o01] * w01
                        + img[o10] * w10 + img[o11] * w11;
                obase[c * (S * S) + orow] = v;
            }
        }
    }
}

extern "C" void kernel_launch(void* const* d_in, const int* in_sizes, int n_in,
                              void* d_out, int out_size) {
    const float* x  = (const float*)d_in[0];
    const float* ox = (const float*)d_in[1];
    const float* oy = (const float*)d_in[2];
    const float* w  = (const float*)d_in[3];
    const void*  mm = d_in[4];

    prep_kernel<<<dim3(B, YCHUNKS), 256>>>(ox, oy, w, mm);

    // Launch deform with programmatic stream serialization (PDL): it may begin
    // launching while prep drains; cudaGridDependencySynchronize() inside the
    // kernel provides the data dependency.
    cudaLaunchConfig_t cfg = {};
    cfg.gridDim  = dim3(S / RPB, B);
    cfg.blockDim = dim3(256, 1, 1);
    cfg.dynamicSmemBytes = 0;
    cfg.stream = 0;  // legacy default stream (same as <<<>>>), under capture

    cudaLaunchAttribute attr[1];
    attr[0].id = cudaLaunchAttributeProgrammaticStreamSerialization;
    attr[0].val.programmaticStreamSerializationAllowed = 1;
    cfg.attrs = attr;
    cfg.numAttrs = 1;

    cudaLaunchKernelEx(&cfg, deform_kernel, x, (float*)d_out);
}